// round 12
// baseline (speedup 1.0000x reference)
#include <cuda_runtime.h>
#include <cuda_bf16.h>
#include <cstdint>

// Correlation cost volume:
// out[b, 9*i+j, h, w] = (1/C) * sum_c x1[b,c,h,w] * x2[b,c,h+i-4,w+j-4]
// B=4, C=256, H=96, W=192, 9x9 grid, zero padding.
// R12 = R11 (TW=64/PW=8, single wave, stride-84 + diagonal lane permutation,
// scalar FFMA) with the loader fix: dummy x2 jobs (qx>=20) issue NO cp.async
// (they were zero-filling into the next row and racing with real data).

#define B_ 4
#define C_ 256
#define H_ 96
#define W_ 192
#define HW_ (H_ * W_)
#define TH 4
#define TW 64
#define PW 8
#define CH 8
#define NCHUNK (C_ / CH)          // 32
#define X2ROWS 12
#define XSTR 84                   // words; %4==0 (16B align), %32==20 (bank math)
#define X2BUF (CH * X2ROWS * XSTR)    // 8064 floats per buffer
#define X1BUF (CH * TH * XSTR)        // 2688 floats per buffer
#define SMEM_FLOATS (2 * X2BUF + 2 * X1BUF)   // 21504 floats = 86016 B
#define NTHREADS 288
#define CHUNK_ELEMS (CH * HW_)
#define X2CHSTRB (X2ROWS * XSTR * 4)    // 4032 B per channel
#define X1CHSTRB (TH * XSTR * 4)        // 1344 B per channel
#define X2BUFB (X2BUF * 4)
#define X1BUFB (X1BUF * 4)

__device__ __forceinline__ void cp_async16(uint32_t dst, const float* src, int sz) {
    asm volatile("cp.async.cg.shared.global [%0], [%1], 16, %2;\n"
                 :: "r"(dst), "l"(src), "r"(sz));
}
__device__ __forceinline__ void cp_commit() {
    asm volatile("cp.async.commit_group;\n");
}
__device__ __forceinline__ void cp_wait1() {
    asm volatile("cp.async.wait_group 1;\n");
}
__device__ __forceinline__ float4 lds128(uint32_t a) {
    float4 v;
    asm("ld.shared.v4.f32 {%0, %1, %2, %3}, [%4];"
        : "=f"(v.x), "=f"(v.y), "=f"(v.z), "=f"(v.w) : "r"(a));
    return v;
}

__global__ __launch_bounds__(NTHREADS, 2)
void corr_kernel(const float* __restrict__ x1,
                 const float* __restrict__ x2,
                 float* __restrict__ out) {
    extern __shared__ float smem[];

    const int w0 = blockIdx.x * TW;   // 0,64,128
    const int h0 = blockIdx.y * TH;
    const int b  = blockIdx.z;

    const int tid  = threadIdx.x;
    const int di   = tid >> 5;        // warp id = row displacement 0..8
    const int lane = tid & 31;

    // diagonal lane permutation: phase p = lane>>3, j = lane&7
    //   wg = j, r = (base[j] + p) & 3, base[j] = (j + 2*(j>>2)) & 3
    // -> every 8-lane LDS.128 phase hits 8 distinct 16B bank groups at
    //    stride 84 (84 % 32 == 20; {8j + 20*pat} all distinct per phase).
    const int jj = lane & 7;
    const int pp = lane >> 3;
    const int r  = ((jj + 2 * (jj >> 2)) + pp) & 3;
    const int wg = jj;
    const int wbase = wg * PW;        // 0..56
    const int rdi  = r + di;          // x2 ext row 0..11

    const float* x1g = x1 + (size_t)b * C_ * HW_;
    const float* x2g = x2 + (size_t)b * C_ * HW_;

    const uint32_t sx2_u = (uint32_t)__cvta_generic_to_shared(smem);
    const uint32_t sx1_u = sx2_u + (uint32_t)(2 * X2BUFB);

    // ---------------- affine loader precompute ----------------
    // x2: CH*12 = 96 rows x 20 real float4 per row. 288 threads = 12 rows x 24
    // thread slots; slots with qx >= 20 are INACTIVE (no cp.async at all —
    // a size-0 cp.async still zero-fills 16B and would clobber the next row).
    const int rr = tid / 24;           // 0..11
    const int qx = tid - rr * 24;      // 0..23; real job iff < 20
    const bool x2on = (qx < 20);
    const int gh  = h0 + rr - 4;
    const int gw0 = w0 - 8 + 4 * qx;
    const bool ok2 = x2on && ((unsigned)gh < (unsigned)H_) &&
                     (gw0 >= 0) && (gw0 <= W_ - 4);
    const int x2size = ok2 ? 16 : 0;   // in-row halo: sz=0 -> 16B zero-fill
    const float* x2s0 = ok2 ? (x2g + ((size_t)gh) * W_ + gw0) : x2g;
    const uint32_t x2d0 = sx2_u + (uint32_t)((rr * XSTR + 4 * qx) * 4);

    // x1: CH*4 = 32 rows x 16 float4 = 512 jobs; threads 0..255, rounds u=0,1:
    //   row = tid>>4 (+16 on round 1), q1 = tid&15.
    const bool do_x1 = (tid < 256);
    const int row1 = tid >> 4;         // 0..15
    const int q1   = tid & 15;
    const int c1a  = row1 >> 2;        // round 1 adds +4 channels
    const int rr1  = row1 & 3;
    const float* x1s0 = x1g + ((size_t)c1a * H_ + (h0 + rr1)) * W_ + w0 + 4 * q1;
    const uint32_t x1d0 = sx1_u + (uint32_t)(((c1a * TH + rr1) * XSTR + 4 * q1) * 4);

    // ---------------- accumulators ----------------
    float acc[9][PW];
    #pragma unroll
    for (int dj = 0; dj < 9; ++dj)
        #pragma unroll
        for (int k = 0; k < PW; ++k) acc[dj][k] = 0.0f;

    // ---- prologue: chunk 0 -> buffer 0 ----
    {
        if (x2on) {
            const float* s2 = x2s0;
            uint32_t d2 = x2d0;
            #pragma unroll
            for (int s = 0; s < 8; ++s) {
                cp_async16(d2, s2, x2size);
                s2 += HW_;
                d2 += X2CHSTRB;
            }
        }
        if (do_x1) {
            cp_async16(x1d0, x1s0, 16);
            cp_async16(x1d0 + 4 * X1CHSTRB, x1s0 + 4 * HW_, 16);
        }
    }
    cp_commit();

    // ---------------- main pipelined loop ----------------
    for (int it = 0; it < NCHUNK; ++it) {
        if (it + 1 < NCHUNK) {
            const int chOff = (it + 1) * CHUNK_ELEMS;
            const uint32_t bo2 = ((it + 1) & 1) ? (uint32_t)X2BUFB : 0u;
            const uint32_t bo1 = ((it + 1) & 1) ? (uint32_t)X1BUFB : 0u;
            if (x2on) {
                const float* s2 = x2s0 + chOff;
                uint32_t d2 = x2d0 + bo2;
                #pragma unroll
                for (int s = 0; s < 8; ++s) {
                    cp_async16(d2, s2, x2size);
                    s2 += HW_;
                    d2 += X2CHSTRB;
                }
            }
            if (do_x1) {
                const float* s1 = x1s0 + chOff;
                uint32_t d1 = x1d0 + bo1;
                cp_async16(d1, s1, 16);
                cp_async16(d1 + 4 * X1CHSTRB, s1 + 4 * HW_, 16);
            }
        }
        cp_commit();
        cp_wait1();
        __syncthreads();

        uint32_t p1 = sx1_u + (uint32_t)((it & 1) * X1BUFB)
                    + (uint32_t)((r * XSTR + wbase) * 4);
        uint32_t p2 = sx2_u + (uint32_t)((it & 1) * X2BUFB)
                    + (uint32_t)((rdi * XSTR + wbase + 4) * 4);

        #pragma unroll
        for (int c = 0; c < CH; ++c) {
            const float4 a0 = lds128(p1);
            const float4 a1 = lds128(p1 + 16);
            const float4 v0 = lds128(p2);
            const float4 v1 = lds128(p2 + 16);
            const float4 v2 = lds128(p2 + 32);
            const float4 v3 = lds128(p2 + 48);
            p1 += X1CHSTRB;
            p2 += X2CHSTRB;
            float a[PW]  = {a0.x, a0.y, a0.z, a0.w, a1.x, a1.y, a1.z, a1.w};
            float xw[16] = {v0.x, v0.y, v0.z, v0.w, v1.x, v1.y, v1.z, v1.w,
                            v2.x, v2.y, v2.z, v2.w, v3.x, v3.y, v3.z, v3.w};
            #pragma unroll
            for (int dj = 0; dj < 9; ++dj)
                #pragma unroll
                for (int k = 0; k < PW; ++k)
                    acc[dj][k] = fmaf(a[k], xw[dj + k], acc[dj][k]);
        }
        __syncthreads();
    }

    // ---------------- epilogue ----------------
    const float scale = 1.0f / (float)C_;
    #pragma unroll
    for (int dj = 0; dj < 9; ++dj) {
        const int d = di * 9 + dj;
        float* o = out + (((size_t)b * 81 + d) * H_ + (h0 + r)) * W_ + w0 + wbase;
        float4 v;
        v.x = acc[dj][0] * scale;
        v.y = acc[dj][1] * scale;
        v.z = acc[dj][2] * scale;
        v.w = acc[dj][3] * scale;
        *reinterpret_cast<float4*>(o) = v;
        v.x = acc[dj][4] * scale;
        v.y = acc[dj][5] * scale;
        v.z = acc[dj][6] * scale;
        v.w = acc[dj][7] * scale;
        *reinterpret_cast<float4*>(o + 4) = v;
    }
}

extern "C" void kernel_launch(void* const* d_in, const int* in_sizes, int n_in,
                              void* d_out, int out_size) {
    const float* x1 = (const float*)d_in[0];
    const float* x2 = (const float*)d_in[1];
    float* out = (float*)d_out;

    static bool attr_set = false;
    if (!attr_set) {
        cudaFuncSetAttribute(corr_kernel,
                             cudaFuncAttributeMaxDynamicSharedMemorySize,
                             SMEM_FLOATS * (int)sizeof(float));
        attr_set = true;
    }

    dim3 grid(W_ / TW, H_ / TH, B_);   // (3, 24, 4) = 288 blocks -> 1 wave
    corr_kernel<<<grid, NTHREADS, SMEM_FLOATS * sizeof(float)>>>(x1, x2, out);
}

// round 14
// speedup vs baseline: 1.2872x; 1.2872x over previous
#include <cuda_runtime.h>
#include <cuda_bf16.h>
#include <cstdint>

// Correlation cost volume:
// out[b, 9*i+j, h, w] = (1/C) * sum_c x1[b,c,h,w] * x2[b,c,h+i-4,w+j-4]
// B=4, C=256, H=96, W=192, 9x9 grid, zero padding.
// R13 = R10's verified loader + scalar-FFMA compute (TW=32, CH=8) with a
// 4-stage cp.async ring: prefetch distance 2, wait_group 2, ONE sync/chunk.

#define B_ 4
#define C_ 256
#define H_ 96
#define W_ 192
#define HW_ (H_ * W_)
#define TH 4
#define TW 32
#define PW 4
#define CH 8
#define NCHUNK (C_ / CH)          // 32
#define NBUF 4
#define X2ROWS 12
#define X2STR 56                  // conflict-free LDS.128
#define X1STR 40                  // conflict-free LDS.128
#define X2BUF (CH * X2ROWS * X2STR)   // 5376 floats per buffer
#define X1BUF (CH * TH * X1STR)       // 1280 floats per buffer
#define SMEM_FLOATS (NBUF * (X2BUF + X1BUF))  // 26624 floats = 106496 B
#define NTHREADS 288
#define CHUNK_ELEMS (CH * HW_)
#define X2CHSTRB (X2ROWS * X2STR * 4)   // 2688
#define X1CHSTRB (TH * X1STR * 4)       // 640
#define X2BUFB (X2BUF * 4)
#define X1BUFB (X1BUF * 4)
#define STAGEB ((X2BUF + X1BUF) * 4)    // bytes per stage (x2 part + x1 part)

__device__ __forceinline__ void cp_async16(uint32_t dst, const float* src, int sz) {
    asm volatile("cp.async.cg.shared.global [%0], [%1], 16, %2;\n"
                 :: "r"(dst), "l"(src), "r"(sz));
}
__device__ __forceinline__ void cp_commit() {
    asm volatile("cp.async.commit_group;\n");
}
__device__ __forceinline__ void cp_wait2() {
    asm volatile("cp.async.wait_group 2;\n");
}
__device__ __forceinline__ float4 lds128(uint32_t a) {
    float4 v;
    asm("ld.shared.v4.f32 {%0, %1, %2, %3}, [%4];"
        : "=f"(v.x), "=f"(v.y), "=f"(v.z), "=f"(v.w) : "r"(a));
    return v;
}

__global__ __launch_bounds__(NTHREADS, 2)
void corr_kernel(const float* __restrict__ x1,
                 const float* __restrict__ x2,
                 float* __restrict__ out) {
    extern __shared__ float smem[];
    // layout: 4 stages of [x2 tile (5376 f) | x1 tile (1280 f)]

    const int w0 = blockIdx.x * TW;
    const int h0 = blockIdx.y * TH;
    const int b  = blockIdx.z;

    const int tid  = threadIdx.x;
    const int di   = tid >> 5;
    const int lane = tid & 31;
    const int r    = lane & 3;
    const int wg   = lane >> 2;
    const int wbase = wg * PW;
    const int rdi  = r + di;

    const float* x1g = x1 + (size_t)b * C_ * HW_;
    const float* x2g = x2 + (size_t)b * C_ * HW_;

    const uint32_t smem_u = (uint32_t)__cvta_generic_to_shared(smem);

    // ---------------- affine loader precompute (verified R9/R10) ----------------
    // x2: CH*12 = 96 rows x 12 float4 = 1152 jobs; qid = tid + 288*s (s=0..3).
    // 288 = 24*12: q = tid%12 fixed, rr = (tid/12)%12 fixed, c = (tid/12)/12 + 2s.
    const int r0  = tid / 12;
    const int qx  = tid - r0 * 12;
    const int c0  = r0 / 12;          // 0..1
    const int rr  = r0 - c0 * 12;     // 0..11
    const int gh  = h0 + rr - 4;
    const int gw0 = w0 - 8 + 4 * qx;
    const bool ok = ((unsigned)gh < (unsigned)H_) && (gw0 >= 0) && (gw0 <= W_ - 4);
    const int x2size = ok ? 16 : 0;   // sz=0 -> in-row 16B zero-fill (halo)
    const float* x2s0 = ok ? (x2g + ((size_t)c0 * H_ + gh) * W_ + gw0) : x2g;
    const uint32_t x2d0 = smem_u + (uint32_t)(((c0 * X2ROWS + rr) * X2STR + 4 * qx) * 4);

    // x1: CH*4 = 32 rows x 8 float4 = 256 jobs, threads 0..255.
    const bool do_x1 = (tid < 256);
    const int c1  = tid >> 5;
    const int rr1 = (tid >> 3) & 3;
    const int q1  = tid & 7;
    const float* x1s0 = x1g + ((size_t)c1 * H_ + (h0 + rr1)) * W_ + w0 + 4 * q1;
    const uint32_t x1d0 = smem_u + (uint32_t)(X2BUFB)
                        + (uint32_t)(((c1 * TH + rr1) * X1STR + 4 * q1) * 4);

    // ---------------- accumulators ----------------
    float acc[9][PW];
    #pragma unroll
    for (int dj = 0; dj < 9; ++dj)
        #pragma unroll
        for (int k = 0; k < PW; ++k) acc[dj][k] = 0.0f;

    // ---- prologue: chunks 0 and 1 into stages 0 and 1 ----
    #pragma unroll
    for (int pk = 0; pk < 2; ++pk) {
        const int chOff = pk * CHUNK_ELEMS;
        const uint32_t so = (uint32_t)pk * STAGEB;
        const float* s2 = x2s0 + chOff;
        uint32_t d2 = x2d0 + so;
        #pragma unroll
        for (int s = 0; s < 4; ++s) {
            cp_async16(d2, s2, x2size);
            s2 += 2 * HW_;
            d2 += 2 * X2CHSTRB;
        }
        if (do_x1) cp_async16(x1d0 + so, x1s0 + chOff, 16);
        cp_commit();
    }

    // ---------------- main loop: prefetch 2, ONE sync per chunk ----------------
    for (int it = 0; it < NCHUNK; ++it) {
        if (it + 2 < NCHUNK) {
            const int chOff = (it + 2) * CHUNK_ELEMS;
            const uint32_t so = (uint32_t)((it + 2) & (NBUF - 1)) * STAGEB;
            const float* s2 = x2s0 + chOff;
            uint32_t d2 = x2d0 + so;
            #pragma unroll
            for (int s = 0; s < 4; ++s) {
                cp_async16(d2, s2, x2size);
                s2 += 2 * HW_;
                d2 += 2 * X2CHSTRB;
            }
            if (do_x1) cp_async16(x1d0 + so, x1s0 + chOff, 16);
        }
        cp_commit();         // unconditional: uniform group counting
        cp_wait2();          // chunk `it` (2 groups back) resident
        __syncthreads();     // visibility of all threads' copies + WAR guard

        const uint32_t so = (uint32_t)(it & (NBUF - 1)) * STAGEB;
        uint32_t p1 = smem_u + so + (uint32_t)X2BUFB
                    + (uint32_t)((r * X1STR + wbase) * 4);
        uint32_t p2 = smem_u + so
                    + (uint32_t)((rdi * X2STR + wbase + 4) * 4);

        #pragma unroll
        for (int c = 0; c < CH; ++c) {
            const float4 av = lds128(p1);
            const float4 v0 = lds128(p2);
            const float4 v1 = lds128(p2 + 16);
            const float4 v2 = lds128(p2 + 32);
            p1 += X1CHSTRB;
            p2 += X2CHSTRB;
            float a[PW] = {av.x, av.y, av.z, av.w};
            float xw[12] = {v0.x, v0.y, v0.z, v0.w,
                            v1.x, v1.y, v1.z, v1.w,
                            v2.x, v2.y, v2.z, v2.w};
            #pragma unroll
            for (int dj = 0; dj < 9; ++dj)
                #pragma unroll
                for (int k = 0; k < PW; ++k)
                    acc[dj][k] = fmaf(a[k], xw[dj + k], acc[dj][k]);
        }
        // no trailing sync: 4-stage ring -> writes at it+? target buffers
        // whose readers are >=2 syncs in the past (proof in header comment)
    }

    // ---------------- epilogue ----------------
    const float scale = 1.0f / (float)C_;
    #pragma unroll
    for (int dj = 0; dj < 9; ++dj) {
        const int d = di * 9 + dj;
        float4 v;
        v.x = acc[dj][0] * scale;
        v.y = acc[dj][1] * scale;
        v.z = acc[dj][2] * scale;
        v.w = acc[dj][3] * scale;
        float* o = out + (((size_t)b * 81 + d) * H_ + (h0 + r)) * W_ + w0 + wbase;
        *reinterpret_cast<float4*>(o) = v;
    }
}

extern "C" void kernel_launch(void* const* d_in, const int* in_sizes, int n_in,
                              void* d_out, int out_size) {
    const float* x1 = (const float*)d_in[0];
    const float* x2 = (const float*)d_in[1];
    float* out = (float*)d_out;

    static bool attr_set = false;
    if (!attr_set) {
        cudaFuncSetAttribute(corr_kernel,
                             cudaFuncAttributeMaxDynamicSharedMemorySize,
                             SMEM_FLOATS * (int)sizeof(float));
        attr_set = true;
    }

    dim3 grid(W_ / TW, H_ / TH, B_);   // (6, 24, 4)
    corr_kernel<<<grid, NTHREADS, SMEM_FLOATS * sizeof(float)>>>(x1, x2, out);
}